// round 16
// baseline (speedup 1.0000x reference)
#include <cuda_runtime.h>
#include <cuda_bf16.h>
#include <mma.h>
#include <cstdint>

using namespace nvcuda;

// ---------------- problem constants ----------------
#define BATCH   32
#define HH      56
#define WW      56
#define CC      256
#define HEADS   8
#define HD      32
#define WIN     7
#define SHIFT   3
#define NN      49
#define NWIN    64
#define NWTOT   (BATCH * NWIN)      // 2048
#define MTOT    (NWTOT * NN)        // 100352
#define XN      (BATCH * HH * WW * CC)   // 25690112 elements

// ---------------- scratch (device globals; device-code refs only) ----------------
__device__ float g_qkv[(size_t)MTOT * 768];
__device__ float g_bias[4 * HEADS * NN * 52];

// bf16 hi/lo split copies (v = hi + lo to ~2^-18 rel)
__device__ __nv_bfloat16 g_xhi[XN],  g_xlo[XN];
__device__ __nv_bfloat16 g_ahi[XN],  g_alo[XN];   // attention output (written by attn)
__device__ __nv_bfloat16 g_wqhi[768 * 256], g_wqlo[768 * 256];
__device__ __nv_bfloat16 g_wphi[256 * 256], g_wplo[256 * 256];

// ---------------- cp.async helpers ----------------
#define CP16(d, s) \
    asm volatile("cp.async.cg.shared.global [%0], [%1], 16;" :: "r"(d), "l"(s))
#define CP_COMMIT() asm volatile("cp.async.commit_group;" ::: "memory")
#define CP_WAIT0()  asm volatile("cp.async.wait_group 0;" ::: "memory")

// Map a flattened window-row index m -> element offset of the source pixel in x.
// roll(+3) inverts roll(-3): same map serves gather (QKV) and scatter (proj).
__device__ __forceinline__ int src_offset(int m) {
    int wq = m / NN;
    int n  = m - wq * NN;
    int b  = wq >> 6;
    int wi = wq & 63;
    int wh = wi >> 3, ww = wi & 7;
    int r = wh * WIN + n / WIN;
    int c = ww * WIN + n % WIN;
    int sh = r + SHIFT; if (sh >= HH) sh -= HH;
    int sw = c + SHIFT; if (sw >= WW) sw -= WW;
    return ((b * HH + sh) * WW + sw) * CC;
}

// =====================================================================
// Kernel 0: fused bias+mask table. 4 classes x 8 heads.
// =====================================================================
__global__ void bias_kernel(const float* __restrict__ tbl,
                            const int* __restrict__ relidx) {
    const int cls = blockIdx.x & 3;
    const int h   = blockIdx.x >> 2;
    for (int idx = threadIdx.x; idx < NN * NN; idx += blockDim.x) {
        int i = idx / NN, j = idx % NN;
        float b = tbl[relidx[idx] * HEADS + h];
        int rhi = (cls & 2) ? ((i / 7 < 4) ? 1 : 2) : 0;
        int rwi = (cls & 1) ? ((i % 7 < 4) ? 1 : 2) : 0;
        int rhj = (cls & 2) ? ((j / 7 < 4) ? 1 : 2) : 0;
        int rwj = (cls & 1) ? ((j % 7 < 4) ? 1 : 2) : 0;
        float msk = ((rhi * 3 + rwi) == (rhj * 3 + rwj)) ? 0.f : -100.f;
        g_bias[((cls * HEADS + h) * NN + i) * 52 + j] = b + msk;
    }
}

// =====================================================================
// Kernel 0b: ONE launch for all fp32 -> bf16 hi/lo splits (grid-partitioned).
//   blocks [0, G0)           : x    -> g_x{hi,lo}
//   blocks [G0, G0+G1)       : qkvw -> g_wq{hi,lo}
//   blocks [G0+G1, G0+G1+G2) : projw-> g_wp{hi,lo}
// =====================================================================
#define CS_G0 (XN / 4 / 256)                 // 25088
#define CS_G1 ((768 * 256) / 4 / 256)        // 192
#define CS_G2 ((256 * 256) / 4 / 256)        // 64

__global__ void convall(const float* __restrict__ x,
                        const float* __restrict__ qkvw,
                        const float* __restrict__ projw) {
    const float* src;
    __nv_bfloat16* hi;
    __nv_bfloat16* lo;
    int i;
    if (blockIdx.x < CS_G0) {
        src = x; hi = g_xhi; lo = g_xlo;
        i = blockIdx.x * 256 + threadIdx.x;
    } else if (blockIdx.x < CS_G0 + CS_G1) {
        src = qkvw; hi = g_wqhi; lo = g_wqlo;
        i = (blockIdx.x - CS_G0) * 256 + threadIdx.x;
    } else {
        src = projw; hi = g_wphi; lo = g_wplo;
        i = (blockIdx.x - CS_G0 - CS_G1) * 256 + threadIdx.x;
    }
    float4 v = ((const float4*)src)[i];
    __nv_bfloat16 h0 = __float2bfloat16(v.x);
    __nv_bfloat16 h1 = __float2bfloat16(v.y);
    __nv_bfloat16 h2 = __float2bfloat16(v.z);
    __nv_bfloat16 h3 = __float2bfloat16(v.w);
    __nv_bfloat16 l0 = __float2bfloat16(v.x - __bfloat162float(h0));
    __nv_bfloat16 l1 = __float2bfloat16(v.y - __bfloat162float(h1));
    __nv_bfloat16 l2 = __float2bfloat16(v.z - __bfloat162float(h2));
    __nv_bfloat16 l3 = __float2bfloat16(v.w - __bfloat162float(h3));
    ((__nv_bfloat162*)hi)[i * 2]     = __nv_bfloat162(h0, h1);
    ((__nv_bfloat162*)hi)[i * 2 + 1] = __nv_bfloat162(h2, h3);
    ((__nv_bfloat162*)lo)[i * 2]     = __nv_bfloat162(l0, l1);
    ((__nv_bfloat162*)lo)[i * 2 + 1] = __nv_bfloat162(l2, l3);
}

// =====================================================================
// WMMA (HMMA) GEMM v2 (unchanged from R15 — proven: pair ~700us):
// 128x128 tile, 256 threads, warp tile 64x32, cp.async double-buffer,
// __launch_bounds__(256, 2) -> 2 CTAs/SM.
// =====================================================================
#define GM_SMEM 81920

template<bool QKV>
__global__ __launch_bounds__(256, 2) void wgemm(const float* __restrict__ bias,
                                                float* __restrict__ OUT) {
    extern __shared__ char dsm[];
    __shared__ int so[128];

    const int n0 = blockIdx.x * 128;
    const int m0 = blockIdx.y * 128;
    const int t  = threadIdx.x;
    const int w  = t >> 5;

    if (t < 128) so[t] = src_offset(m0 + t);
    __syncthreads();

    const int row = t >> 1;
    const int kh  = t & 1;
    const __nv_bfloat16 *Ahi, *Alo, *Bhi, *Blo;
    size_t abase;
    if (QKV) { Ahi = g_xhi; Alo = g_xlo; Bhi = g_wqhi; Blo = g_wqlo;
               abase = (size_t)so[row]; }
    else     { Ahi = g_ahi; Alo = g_alo; Bhi = g_wphi; Blo = g_wplo;
               abase = (size_t)(m0 + row) * 256; }
    const size_t bbase = (size_t)(n0 + row) * 256;
    const uint32_t dsmem = (uint32_t)__cvta_generic_to_shared(dsm);
    const uint32_t arow  = (uint32_t)row * 80u + (uint32_t)kh * 32u;

    auto issue = [&](int blk, uint32_t bufoff) {
        const size_t go = (size_t)blk * 32 + kh * 16;
        const uint32_t d = dsmem + bufoff + arow;
        CP16(d,              Ahi + abase + go);
        CP16(d + 16,         Ahi + abase + go + 8);
        CP16(d + 10240,      Alo + abase + go);
        CP16(d + 10240 + 16, Alo + abase + go + 8);
        CP16(d + 20480,      Bhi + bbase + go);
        CP16(d + 20480 + 16, Bhi + bbase + go + 8);
        CP16(d + 30720,      Blo + bbase + go);
        CP16(d + 30720 + 16, Blo + bbase + go + 8);
    };

    const int wm = w & 1;
    const int wn = w >> 1;

    wmma::fragment<wmma::accumulator, 16, 16, 16, float> c[4][2];
#pragma unroll
    for (int i = 0; i < 4; i++)
#pragma unroll
        for (int j = 0; j < 2; j++) wmma::fill_fragment(c[i][j], 0.f);

    issue(0, 0);
    CP_COMMIT();

#pragma unroll 1
    for (int blk = 0; blk < 8; ++blk) {
        CP_WAIT0();
        __syncthreads();
        if (blk < 7) {
            issue(blk + 1, (uint32_t)((blk + 1) & 1) * 40960u);
            CP_COMMIT();
        }

        char* bb = dsm + (blk & 1) * 40960;
#pragma unroll
        for (int ks = 0; ks < 32; ks += 16) {
            wmma::fragment<wmma::matrix_a, 16, 16, 16, __nv_bfloat16, wmma::row_major> ah[4], al[4];
#pragma unroll
            for (int i = 0; i < 4; i++) {
                const __nv_bfloat16* ap =
                    (const __nv_bfloat16*)(bb + (wm * 64 + i * 16) * 80) + ks;
                wmma::load_matrix_sync(ah[i], ap, 40);
                wmma::load_matrix_sync(al[i], ap + 5120, 40);
            }
#pragma unroll
            for (int j = 0; j < 2; j++) {
                wmma::fragment<wmma::matrix_b, 16, 16, 16, __nv_bfloat16, wmma::col_major> bh, bl;
                const __nv_bfloat16* bp =
                    (const __nv_bfloat16*)(bb + 20480 + (wn * 32 + j * 16) * 80) + ks;
                wmma::load_matrix_sync(bh, bp, 40);
                wmma::load_matrix_sync(bl, bp + 5120, 40);
#pragma unroll
                for (int i = 0; i < 4; i++) {
                    wmma::mma_sync(c[i][j], ah[i], bh, c[i][j]);
                    wmma::mma_sync(c[i][j], ah[i], bl, c[i][j]);
                    wmma::mma_sync(c[i][j], al[i], bh, c[i][j]);
                }
            }
        }
    }

    __syncthreads();
    float* co = (float*)dsm;
#pragma unroll
    for (int i = 0; i < 4; i++)
#pragma unroll
        for (int j = 0; j < 2; j++)
            wmma::store_matrix_sync(&co[(wm * 64 + i * 16) * 132 + wn * 32 + j * 16],
                                    c[i][j], 132, wmma::mem_row_major);
    __syncthreads();

    const float* cs = &co[row * 132 + kh * 64];
    float* gdst;
    if (QKV) gdst = g_qkv + (size_t)(m0 + row) * 768 + n0 + kh * 64;
    else     gdst = OUT + so[row] + n0 + kh * 64;
#pragma unroll
    for (int jj = 0; jj < 16; ++jj) {
        float4 bv = *(const float4*)(bias + n0 + kh * 64 + jj * 4);
        float4 o  = *(const float4*)(cs + jj * 4);
        o.x += bv.x; o.y += bv.y; o.z += bv.z; o.w += bv.w;
        *(float4*)(gdst + jj * 4) = o;
    }
}

// =====================================================================
// Kernel 2: windowed attention v3. One block per (window, head).
// FUSED score+softmax: warp w handles rows {w, w+8, ...}; lane covers
// j = lane and j+32; scores stay in registers through the shuffle-softmax;
// only final P hits sS. Deletes one __syncthreads + the sS score round-trip.
// kT row stride 64 so the lane+32 column stays in-row, conflict-free.
// Epilogue writes the bf16 hi/lo split directly (feeds proj wgemm).
// =====================================================================
__global__ __launch_bounds__(256) void attn_kernel() {
    __shared__ float qs[NN * HD];
    __shared__ float vs[NN * HD];
    __shared__ float kT[HD * 64];
    __shared__ float sS[NN * 52];

    const int w = blockIdx.x >> 3;
    const int h = blockIdx.x & 7;
    const int t = threadIdx.x;

    const int wi = w & 63;
    const int cls = (((wi >> 3) == 7) ? 2 : 0) | (((wi & 7) == 7) ? 1 : 0);
    const float* gb = g_bias + (size_t)((cls * HEADS + h) * NN) * 52;

    const float* base = g_qkv + (size_t)w * NN * 768 + h * HD;
    for (int idx = t; idx < NN * 8; idx += 256) {
        int n = idx >> 3, dq = idx & 7;
        const float4* p = (const float4*)(base + n * 768 + dq * 4);
        float4 q4 = p[0];
        float4 k4 = p[64];
        float4 v4 = p[128];
        *(float4*)&qs[n * HD + dq * 4] = q4;
        *(float4*)&vs[n * HD + dq * 4] = v4;
        kT[(dq * 4 + 0) * 64 + n] = k4.x;
        kT[(dq * 4 + 1) * 64 + n] = k4.y;
        kT[(dq * 4 + 2) * 64 + n] = k4.z;
        kT[(dq * 4 + 3) * 64 + n] = k4.w;
    }
    __syncthreads();

    // ---- fused scores + softmax: one warp per row ----
    const int lane = t & 31, w8 = t >> 5;
    const float scale = 0.17677669529663687f;
    const bool hasj2 = (lane + 32) < NN;
    for (int i = w8; i < NN; i += 8) {
        float ax = 0.f, ay = 0.f;
#pragma unroll
        for (int k = 0; k < HD; k++) {
            float qv = qs[i * HD + k];               // broadcast
            ax += qv * kT[k * 64 + lane];            // j = lane
            ay += qv * kT[k * 64 + lane + 32];       // j = lane+32 (junk if >=NN)
        }
        float e0 = ax * scale + __ldg(&gb[i * 52 + lane]);
        float e1 = hasj2 ? (ay * scale + __ldg(&gb[i * 52 + lane + 32])) : -1e30f;
        float mx = fmaxf(e0, e1);
#pragma unroll
        for (int o = 16; o; o >>= 1) mx = fmaxf(mx, __shfl_xor_sync(0xffffffffu, mx, o));
        e0 = __expf(e0 - mx);
        e1 = hasj2 ? __expf(e1 - mx) : 0.f;
        float sm = e0 + e1;
#pragma unroll
        for (int o = 16; o; o >>= 1) sm += __shfl_xor_sync(0xffffffffu, sm, o);
        float inv = 1.f / sm;
        sS[i * 52 + lane] = e0 * inv;
        if (hasj2) sS[i * 52 + lane + 32] = e1 * inv;
    }
    __syncthreads();

    // ---- P @ V: 16 i-groups x 16 d-pairs; write bf16 hi/lo split ----
    const int dp = (t & 15) * 2;
    const int ig = t >> 4;
    const size_t obase = (size_t)w * NN * 256 + h * HD + dp;
    for (int i = ig; i < NN; i += 16) {
        float ax = 0.f, ay = 0.f;
#pragma unroll
        for (int jj = 0; jj < NN; jj++) {
            float p = sS[i * 52 + jj];                       // broadcast
            float2 v2 = *(const float2*)&vs[jj * HD + dp];   // conflict-free pairs
            ax += p * v2.x;
            ay += p * v2.y;
        }
        __nv_bfloat16 hx = __float2bfloat16(ax);
        __nv_bfloat16 hy = __float2bfloat16(ay);
        __nv_bfloat162 hi2(hx, hy);
        __nv_bfloat162 lo2(__float2bfloat16(ax - __bfloat162float(hx)),
                           __float2bfloat16(ay - __bfloat162float(hy)));
        *(__nv_bfloat162*)(g_ahi + obase + (size_t)i * 256) = hi2;
        *(__nv_bfloat162*)(g_alo + obase + (size_t)i * 256) = lo2;
    }
}

// =====================================================================
extern "C" void kernel_launch(void* const* d_in, const int* in_sizes, int n_in,
                              void* d_out, int out_size) {
    const float* x     = (const float*)d_in[0];
    const float* qkvw  = (const float*)d_in[1];
    const float* qkvb  = (const float*)d_in[2];
    const float* projw = (const float*)d_in[3];
    const float* projb = (const float*)d_in[4];
    const float* tbl   = (const float*)d_in[5];
    const int*   ridx  = (const int*)d_in[6];
    float* out = (float*)d_out;

    (void)in_sizes; (void)n_in; (void)out_size;

    cudaFuncSetAttribute(wgemm<true>,  cudaFuncAttributeMaxDynamicSharedMemorySize, GM_SMEM);
    cudaFuncSetAttribute(wgemm<false>, cudaFuncAttributeMaxDynamicSharedMemorySize, GM_SMEM);

    bias_kernel<<<32, 256>>>(tbl, ridx);
    convall<<<CS_G0 + CS_G1 + CS_G2, 256>>>(x, qkvw, projw);

    wgemm<true><<<dim3(6, MTOT / 128), 256, GM_SMEM>>>(qkvb, nullptr);
    attn_kernel<<<NWTOT * HEADS, 256>>>();
    wgemm<false><<<dim3(2, MTOT / 128), 256, GM_SMEM>>>(projb, out);
}